// round 1
// baseline (speedup 1.0000x reference)
#include <cuda_runtime.h>
#include <math.h>

// Problem constants (B=4, S=4096, D=768)
#define D_HALF 768
#define D_FULL 1536
#define NTHREADS 256
#define ELEMS_PER_THREAD 3   // 768 / 256
#define NWARPS 8
#define LN_EPS 1e-5f

// Row-independent precomputed constants:
// [0] = sum(gamma * w0)          [1] = sum(gamma * w1)
// [2] = sum(beta  * w0) + b0     [3] = sum(beta  * w1) + b1
__device__ float g_row_const[4];

__device__ __forceinline__ float4 warp_reduce4(float4 v) {
#pragma unroll
    for (int o = 16; o > 0; o >>= 1) {
        v.x += __shfl_down_sync(0xffffffffu, v.x, o);
        v.y += __shfl_down_sync(0xffffffffu, v.y, o);
        v.z += __shfl_down_sync(0xffffffffu, v.z, o);
        v.w += __shfl_down_sync(0xffffffffu, v.w, o);
    }
    return v;
}

// ---------------------------------------------------------------------------
// Prologue: compute the 4 row-independent constants. One block.
// ---------------------------------------------------------------------------
__global__ void gate_const_kernel(const float* __restrict__ gamma,
                                  const float* __restrict__ beta,
                                  const float* __restrict__ gate_w,
                                  const float* __restrict__ gate_b) {
    __shared__ float4 sh[NWARPS];
    float4 acc = make_float4(0.f, 0.f, 0.f, 0.f);
    for (int j = threadIdx.x; j < D_FULL; j += NTHREADS) {
        float g  = gamma[j];
        float be = beta[j];
        float w0 = gate_w[j];
        float w1 = gate_w[D_FULL + j];
        acc.x += g  * w0;
        acc.y += g  * w1;
        acc.z += be * w0;
        acc.w += be * w1;
    }
    acc = warp_reduce4(acc);
    int wid = threadIdx.x >> 5, lid = threadIdx.x & 31;
    if (lid == 0) sh[wid] = acc;
    __syncthreads();
    if (wid == 0) {
        acc = (lid < NWARPS) ? sh[lid] : make_float4(0.f, 0.f, 0.f, 0.f);
        acc = warp_reduce4(acc);
        if (lid == 0) {
            g_row_const[0] = acc.x;
            g_row_const[1] = acc.y;
            g_row_const[2] = acc.z + gate_b[0];
            g_row_const[3] = acc.w + gate_b[1];
        }
    }
}

// ---------------------------------------------------------------------------
// Main fused kernel: one block per row. Single pass over seq/msa.
//   h = concat(seq, msa);  LN(h);  logits = hn @ W^T + b;  softmax;
//   out = w0*seq + w1*msa
// Using:  logit_k = rstd*(dot_k - mean*Sgw_k) + C_k
//   where dot_k = sum_d h_d * gamma_d * w_k[d]
// ---------------------------------------------------------------------------
__global__ __launch_bounds__(NTHREADS)
void attention_fusion_kernel(const float* __restrict__ seq,
                             const float* __restrict__ msa,
                             const float* __restrict__ gamma,
                             const float* __restrict__ gate_w,
                             float* __restrict__ out) {
    __shared__ float4 sh[NWARPS];
    __shared__ float sh_w0;

    const long long row = blockIdx.x;
    const float* sp = seq + row * D_HALF;
    const float* mp = msa + row * D_HALF;
    float*       op = out + row * D_HALF;

    float sv[ELEMS_PER_THREAD], mv[ELEMS_PER_THREAD];
    float4 acc = make_float4(0.f, 0.f, 0.f, 0.f); // sum, sumsq, dot0, dot1

#pragma unroll
    for (int i = 0; i < ELEMS_PER_THREAD; i++) {
        int j = threadIdx.x + i * NTHREADS;      // 0..767
        float s = sp[j];
        float m = mp[j];
        sv[i] = s;
        mv[i] = m;
        float gs  = __ldg(&gamma[j]);
        float gm  = __ldg(&gamma[D_HALF + j]);
        float w0s = __ldg(&gate_w[j]);
        float w0m = __ldg(&gate_w[D_HALF + j]);
        float w1s = __ldg(&gate_w[D_FULL + j]);
        float w1m = __ldg(&gate_w[D_FULL + D_HALF + j]);
        acc.x += s + m;
        acc.y += fmaf(s, s, m * m);
        acc.z += fmaf(s, gs * w0s, m * gm * w0m);
        acc.w += fmaf(s, gs * w1s, m * gm * w1m);
    }

    // Block reduction of the 4 accumulators
    acc = warp_reduce4(acc);
    int wid = threadIdx.x >> 5, lid = threadIdx.x & 31;
    if (lid == 0) sh[wid] = acc;
    __syncthreads();
    if (wid == 0) {
        acc = (lid < NWARPS) ? sh[lid] : make_float4(0.f, 0.f, 0.f, 0.f);
        acc = warp_reduce4(acc);
        if (lid == 0) {
            const float inv_n = 1.0f / (float)D_FULL;
            float mean = acc.x * inv_n;
            float var  = fmaf(-mean, mean, acc.y * inv_n);
            float rstd = rsqrtf(var + LN_EPS);
            float l0 = fmaf(rstd, acc.z - mean * g_row_const[0], g_row_const[2]);
            float l1 = fmaf(rstd, acc.w - mean * g_row_const[1], g_row_const[3]);
            // softmax over 2: w0 = 1 / (1 + exp(l1 - l0))
            sh_w0 = 1.0f / (1.0f + __expf(l1 - l0));
        }
    }
    __syncthreads();

    float w0 = sh_w0;
    float w1 = 1.0f - w0;
#pragma unroll
    for (int i = 0; i < ELEMS_PER_THREAD; i++) {
        int j = threadIdx.x + i * NTHREADS;
        op[j] = fmaf(w0, sv[i], w1 * mv[i]);
    }
}

// ---------------------------------------------------------------------------
// Launch
// ---------------------------------------------------------------------------
extern "C" void kernel_launch(void* const* d_in, const int* in_sizes, int n_in,
                              void* d_out, int out_size) {
    const float* seq    = (const float*)d_in[0];
    const float* msa    = (const float*)d_in[1];
    const float* gamma  = (const float*)d_in[2];
    const float* beta   = (const float*)d_in[3];
    const float* gate_w = (const float*)d_in[4];
    const float* gate_b = (const float*)d_in[5];
    float* out = (float*)d_out;

    int rows = in_sizes[0] / D_HALF;   // B*S = 16384

    gate_const_kernel<<<1, NTHREADS>>>(gamma, beta, gate_w, gate_b);
    attention_fusion_kernel<<<rows, NTHREADS>>>(seq, msa, gamma, gate_w, out);
}

// round 2
// speedup vs baseline: 1.2722x; 1.2722x over previous
#include <cuda_runtime.h>
#include <math.h>

// Problem constants (B=4, S=4096, D=768)
#define D_HALF 768
#define D_FULL 1536
#define V_HALF 192            // 768 / 4 float4s per half-row
#define NT_MAIN 192           // one float4 per thread
#define NWARPS_MAIN 6
#define NT_PRE 256
#define LN_EPS 1e-5f

// Row-independent constants:
// [0] = sum(gamma*w0)   [1] = sum(gamma*w1)
// [2] = sum(beta*w0)+b0 [3] = sum(beta*w1)+b1
__device__ float  g_row_const[4];
// Precomputed gamma*w products, float4-aligned: gw0[j]=gamma[j]*w0[j], gw1[j]=gamma[j]*w1[j]
__device__ __align__(16) float g_gw0[D_FULL];
__device__ __align__(16) float g_gw1[D_FULL];

__device__ __forceinline__ float4 ldcs4(const float4* p) {
    float4 v;
    asm volatile("ld.global.cs.v4.f32 {%0,%1,%2,%3}, [%4];"
                 : "=f"(v.x), "=f"(v.y), "=f"(v.z), "=f"(v.w) : "l"(p));
    return v;
}
__device__ __forceinline__ void stcs4(float4* p, float4 v) {
    asm volatile("st.global.cs.v4.f32 [%0], {%1,%2,%3,%4};"
                 :: "l"(p), "f"(v.x), "f"(v.y), "f"(v.z), "f"(v.w));
}

__device__ __forceinline__ float4 warp_reduce4(float4 v) {
#pragma unroll
    for (int o = 16; o > 0; o >>= 1) {
        v.x += __shfl_down_sync(0xffffffffu, v.x, o);
        v.y += __shfl_down_sync(0xffffffffu, v.y, o);
        v.z += __shfl_down_sync(0xffffffffu, v.z, o);
        v.w += __shfl_down_sync(0xffffffffu, v.w, o);
    }
    return v;
}

// ---------------------------------------------------------------------------
// Prologue: row-independent constants + gamma*w product arrays. One block.
// ---------------------------------------------------------------------------
__global__ void gate_const_kernel(const float* __restrict__ gamma,
                                  const float* __restrict__ beta,
                                  const float* __restrict__ gate_w,
                                  const float* __restrict__ gate_b) {
    __shared__ float4 sh[NT_PRE / 32];
    float4 acc = make_float4(0.f, 0.f, 0.f, 0.f);
    for (int j = threadIdx.x; j < D_FULL; j += NT_PRE) {
        float g  = gamma[j];
        float be = beta[j];
        float w0 = gate_w[j];
        float w1 = gate_w[D_FULL + j];
        g_gw0[j] = g * w0;
        g_gw1[j] = g * w1;
        acc.x += g  * w0;
        acc.y += g  * w1;
        acc.z += be * w0;
        acc.w += be * w1;
    }
    acc = warp_reduce4(acc);
    int wid = threadIdx.x >> 5, lid = threadIdx.x & 31;
    if (lid == 0) sh[wid] = acc;
    __syncthreads();
    if (wid == 0) {
        acc = (lid < NT_PRE / 32) ? sh[lid] : make_float4(0.f, 0.f, 0.f, 0.f);
        acc = warp_reduce4(acc);
        if (lid == 0) {
            g_row_const[0] = acc.x;
            g_row_const[1] = acc.y;
            g_row_const[2] = acc.z + gate_b[0];
            g_row_const[3] = acc.w + gate_b[1];
        }
    }
}

// ---------------------------------------------------------------------------
// Main fused kernel: one 192-thread block per row, float4 throughout.
// ---------------------------------------------------------------------------
__global__ __launch_bounds__(NT_MAIN)
void attention_fusion_kernel(const float4* __restrict__ seq,
                             const float4* __restrict__ msa,
                             float4* __restrict__ out) {
    __shared__ float4 sh[NWARPS_MAIN];
    __shared__ float sh_w0;

    const long long row = blockIdx.x;
    const int t = threadIdx.x;                 // 0..191
    const float4* sp = seq + row * V_HALF;
    const float4* mp = msa + row * V_HALF;
    float4*       op = out + row * V_HALF;

    const float4* gw0v = (const float4*)g_gw0;
    const float4* gw1v = (const float4*)g_gw1;

    float4 s = ldcs4(sp + t);
    float4 m = ldcs4(mp + t);
    float4 g0s = gw0v[t];
    float4 g0m = gw0v[V_HALF + t];
    float4 g1s = gw1v[t];
    float4 g1m = gw1v[V_HALF + t];

    float4 acc; // x=sum, y=sumsq, z=dot0, w=dot1
    acc.x = (s.x + s.y + s.z + s.w) + (m.x + m.y + m.z + m.w);
    acc.y = s.x*s.x + s.y*s.y + s.z*s.z + s.w*s.w
          + m.x*m.x + m.y*m.y + m.z*m.z + m.w*m.w;
    acc.z = s.x*g0s.x + s.y*g0s.y + s.z*g0s.z + s.w*g0s.w
          + m.x*g0m.x + m.y*g0m.y + m.z*g0m.z + m.w*g0m.w;
    acc.w = s.x*g1s.x + s.y*g1s.y + s.z*g1s.z + s.w*g1s.w
          + m.x*g1m.x + m.y*g1m.y + m.z*g1m.z + m.w*g1m.w;

    acc = warp_reduce4(acc);
    int wid = t >> 5, lid = t & 31;
    if (lid == 0) sh[wid] = acc;
    __syncthreads();
    if (wid == 0) {
        acc = (lid < NWARPS_MAIN) ? sh[lid] : make_float4(0.f, 0.f, 0.f, 0.f);
        acc = warp_reduce4(acc);
        if (lid == 0) {
            const float inv_n = 1.0f / (float)D_FULL;
            float mean = acc.x * inv_n;
            float var  = fmaf(-mean, mean, acc.y * inv_n);
            float rstd = rsqrtf(var + LN_EPS);
            float l0 = fmaf(rstd, acc.z - mean * g_row_const[0], g_row_const[2]);
            float l1 = fmaf(rstd, acc.w - mean * g_row_const[1], g_row_const[3]);
            sh_w0 = 1.0f / (1.0f + __expf(l1 - l0));
        }
    }
    __syncthreads();

    float w0 = sh_w0;
    float w1 = 1.0f - w0;
    float4 o;
    o.x = fmaf(w0, s.x, w1 * m.x);
    o.y = fmaf(w0, s.y, w1 * m.y);
    o.z = fmaf(w0, s.z, w1 * m.z);
    o.w = fmaf(w0, s.w, w1 * m.w);
    stcs4(op + t, o);
}

// ---------------------------------------------------------------------------
// Launch
// ---------------------------------------------------------------------------
extern "C" void kernel_launch(void* const* d_in, const int* in_sizes, int n_in,
                              void* d_out, int out_size) {
    const float* seq    = (const float*)d_in[0];
    const float* msa    = (const float*)d_in[1];
    const float* gamma  = (const float*)d_in[2];
    const float* beta   = (const float*)d_in[3];
    const float* gate_w = (const float*)d_in[4];
    const float* gate_b = (const float*)d_in[5];
    float* out = (float*)d_out;

    int rows = in_sizes[0] / D_HALF;   // B*S = 16384

    gate_const_kernel<<<1, NT_PRE>>>(gamma, beta, gate_w, gate_b);
    attention_fusion_kernel<<<rows, NT_MAIN>>>((const float4*)seq,
                                               (const float4*)msa,
                                               (float4*)out);
}

// round 3
// speedup vs baseline: 1.3361x; 1.0502x over previous
#include <cuda_runtime.h>
#include <math.h>

// Problem constants (B=4, S=4096, D=768)
#define D_HALF 768
#define D_FULL 1536
#define V_HALF 192            // 768 / 4 float4s per half-row
#define NT_MAIN 192           // one float4 column per thread
#define NWARPS_MAIN 6
#define ROWS_PER_BLOCK 4
#define NT_PRE 256
#define LN_EPS 1e-5f

// Row-independent constants:
// [0] = sum(gamma*w0)   [1] = sum(gamma*w1)
// [2] = sum(beta*w0)+b0 [3] = sum(beta*w1)+b1
__device__ float  g_row_const[4];
// Precomputed products: gw0[j]=gamma[j]*w0[j], gw1[j]=gamma[j]*w1[j]
__device__ __align__(16) float g_gw0[D_FULL];
__device__ __align__(16) float g_gw1[D_FULL];

__device__ __forceinline__ float4 ldcs4(const float4* p) {
    float4 v;
    asm volatile("ld.global.cs.v4.f32 {%0,%1,%2,%3}, [%4];"
                 : "=f"(v.x), "=f"(v.y), "=f"(v.z), "=f"(v.w) : "l"(p));
    return v;
}
__device__ __forceinline__ void stcs4(float4* p, float4 v) {
    asm volatile("st.global.cs.v4.f32 [%0], {%1,%2,%3,%4};"
                 :: "l"(p), "f"(v.x), "f"(v.y), "f"(v.z), "f"(v.w));
}

__device__ __forceinline__ float4 warp_reduce4(float4 v) {
#pragma unroll
    for (int o = 16; o > 0; o >>= 1) {
        v.x += __shfl_down_sync(0xffffffffu, v.x, o);
        v.y += __shfl_down_sync(0xffffffffu, v.y, o);
        v.z += __shfl_down_sync(0xffffffffu, v.z, o);
        v.w += __shfl_down_sync(0xffffffffu, v.w, o);
    }
    return v;
}

// ---------------------------------------------------------------------------
// Prologue: row-independent constants + gamma*w product arrays. One block.
// ---------------------------------------------------------------------------
__global__ void gate_const_kernel(const float* __restrict__ gamma,
                                  const float* __restrict__ beta,
                                  const float* __restrict__ gate_w,
                                  const float* __restrict__ gate_b) {
    __shared__ float4 sh[NT_PRE / 32];
    float4 acc = make_float4(0.f, 0.f, 0.f, 0.f);
    for (int j = threadIdx.x; j < D_FULL; j += NT_PRE) {
        float g  = gamma[j];
        float be = beta[j];
        float w0 = gate_w[j];
        float w1 = gate_w[D_FULL + j];
        g_gw0[j] = g * w0;
        g_gw1[j] = g * w1;
        acc.x += g  * w0;
        acc.y += g  * w1;
        acc.z += be * w0;
        acc.w += be * w1;
    }
    acc = warp_reduce4(acc);
    int wid = threadIdx.x >> 5, lid = threadIdx.x & 31;
    if (lid == 0) sh[wid] = acc;
    __syncthreads();
    if (wid == 0) {
        acc = (lid < NT_PRE / 32) ? sh[lid] : make_float4(0.f, 0.f, 0.f, 0.f);
        acc = warp_reduce4(acc);
        if (lid == 0) {
            g_row_const[0] = acc.x;
            g_row_const[1] = acc.y;
            g_row_const[2] = acc.z + gate_b[0];
            g_row_const[3] = acc.w + gate_b[1];
        }
    }
}

// ---------------------------------------------------------------------------
// Main fused kernel: 192 threads, ROWS_PER_BLOCK rows per block.
// Params loaded once per block into registers, reused for all rows.
// ---------------------------------------------------------------------------
__global__ __launch_bounds__(NT_MAIN)
void attention_fusion_kernel(const float4* __restrict__ seq,
                             const float4* __restrict__ msa,
                             float4* __restrict__ out) {
    __shared__ float4 sh[ROWS_PER_BLOCK][NWARPS_MAIN];
    __shared__ float sh_w0[ROWS_PER_BLOCK];

    const int t = threadIdx.x;                 // 0..191
    const long long base = (long long)blockIdx.x * ROWS_PER_BLOCK;
    const float4* sp = seq + base * V_HALF + t;
    const float4* mp = msa + base * V_HALF + t;
    float4*       op = out + base * V_HALF + t;

    const float4* gw0v = (const float4*)g_gw0;
    const float4* gw1v = (const float4*)g_gw1;

    // Params: once per block
    const float4 g0s = gw0v[t];
    const float4 g0m = gw0v[V_HALF + t];
    const float4 g1s = gw1v[t];
    const float4 g1m = gw1v[V_HALF + t];

    // Batch all data loads (MLP = 8 LDG.128)
    float4 s[ROWS_PER_BLOCK], m[ROWS_PER_BLOCK];
#pragma unroll
    for (int r = 0; r < ROWS_PER_BLOCK; r++) {
        s[r] = ldcs4(sp + r * V_HALF);
        m[r] = ldcs4(mp + r * V_HALF);
    }

    // Per-row accumulators: x=sum, y=sumsq, z=dot0, w=dot1
    float4 acc[ROWS_PER_BLOCK];
#pragma unroll
    for (int r = 0; r < ROWS_PER_BLOCK; r++) {
        float4 sv = s[r], mv = m[r];
        float4 a;
        a.x = (sv.x + sv.y + sv.z + sv.w) + (mv.x + mv.y + mv.z + mv.w);
        a.y = sv.x*sv.x + sv.y*sv.y + sv.z*sv.z + sv.w*sv.w
            + mv.x*mv.x + mv.y*mv.y + mv.z*mv.z + mv.w*mv.w;
        a.z = sv.x*g0s.x + sv.y*g0s.y + sv.z*g0s.z + sv.w*g0s.w
            + mv.x*g0m.x + mv.y*g0m.y + mv.z*g0m.z + mv.w*g0m.w;
        a.w = sv.x*g1s.x + sv.y*g1s.y + sv.z*g1s.z + sv.w*g1s.w
            + mv.x*g1m.x + mv.y*g1m.y + mv.z*g1m.z + mv.w*g1m.w;
        acc[r] = warp_reduce4(a);
    }

    const int wid = t >> 5, lid = t & 31;
    if (lid == 0) {
#pragma unroll
        for (int r = 0; r < ROWS_PER_BLOCK; r++) sh[r][wid] = acc[r];
    }
    __syncthreads();

    // Warps 0..3 finalize one row each (6 partials -> scalar w0)
    if (wid < ROWS_PER_BLOCK) {
        float4 a = (lid < NWARPS_MAIN) ? sh[wid][lid]
                                       : make_float4(0.f, 0.f, 0.f, 0.f);
#pragma unroll
        for (int o = 4; o > 0; o >>= 1) {
            a.x += __shfl_down_sync(0xffffffffu, a.x, o);
            a.y += __shfl_down_sync(0xffffffffu, a.y, o);
            a.z += __shfl_down_sync(0xffffffffu, a.z, o);
            a.w += __shfl_down_sync(0xffffffffu, a.w, o);
        }
        if (lid == 0) {
            const float inv_n = 1.0f / (float)D_FULL;
            float mean = a.x * inv_n;
            float var  = fmaf(-mean, mean, a.y * inv_n);
            float rstd = rsqrtf(var + LN_EPS);
            float l0 = fmaf(rstd, a.z - mean * g_row_const[0], g_row_const[2]);
            float l1 = fmaf(rstd, a.w - mean * g_row_const[1], g_row_const[3]);
            sh_w0[wid] = 1.0f / (1.0f + __expf(l1 - l0));
        }
    }
    __syncthreads();

#pragma unroll
    for (int r = 0; r < ROWS_PER_BLOCK; r++) {
        float w0 = sh_w0[r];
        float w1 = 1.0f - w0;
        float4 o;
        o.x = fmaf(w0, s[r].x, w1 * m[r].x);
        o.y = fmaf(w0, s[r].y, w1 * m[r].y);
        o.z = fmaf(w0, s[r].z, w1 * m[r].z);
        o.w = fmaf(w0, s[r].w, w1 * m[r].w);
        stcs4(op + r * V_HALF, o);
    }
}

// ---------------------------------------------------------------------------
// Launch
// ---------------------------------------------------------------------------
extern "C" void kernel_launch(void* const* d_in, const int* in_sizes, int n_in,
                              void* d_out, int out_size) {
    const float* seq    = (const float*)d_in[0];
    const float* msa    = (const float*)d_in[1];
    const float* gamma  = (const float*)d_in[2];
    const float* beta   = (const float*)d_in[3];
    const float* gate_w = (const float*)d_in[4];
    const float* gate_b = (const float*)d_in[5];
    float* out = (float*)d_out;

    int rows   = in_sizes[0] / D_HALF;          // B*S = 16384
    int blocks = rows / ROWS_PER_BLOCK;         // 4096

    gate_const_kernel<<<1, NT_PRE>>>(gamma, beta, gate_w, gate_b);
    attention_fusion_kernel<<<blocks, NT_MAIN>>>((const float4*)seq,
                                                 (const float4*)msa,
                                                 (float4*)out);
}